// round 14
// baseline (speedup 1.0000x reference)
#include <cuda_runtime.h>
#include <cuda_fp16.h>
#include <cstdint>

#define N_NODES 50000
#define N_EDGES 800000
#define IN_F    256
#define OUT_F   64
#define E4      (N_EDGES / 4)          // 200000
#define GEMM_BLOCKS 391                // ceil(50000/128)
#define CSR_BLOCKS  53
#define NB (GEMM_BLOCKS + CSR_BLOCKS)  // 444 = 148 SMs * 3 -> one wave
#define SBH 264                        // sB stride in halves (LDSM conflict-free)
#define AWS 24                         // per-warp A slab row stride in halves

// Scratch (device globals: allocation-guard compliant, zero-init at load)
__device__ __half g_hw[(size_t)N_NODES * OUT_F];  // projected*norm feats (fp16)
__device__ int    g_deg[N_NODES];                 // in-degree (zeroed by aggregate)
__device__ int    g_start[N_NODES];               // CSR row starts
__device__ int    g_slot[N_EDGES];                // per-edge slot within dst bucket
__device__ int    g_esrc[N_EDGES];                // src ids bucketed by dst
__device__ int    g_bsum[CSR_BLOCKS];             // CSR per-block sums
__device__ int    g_boff[CSR_BLOCKS];             // scanned block offsets
// Sense-reversing barrier state (zero-init; self-consistent across replays)
__device__ unsigned g_cnt_all, g_sense_all;
__device__ unsigned g_cnt_csr, g_sense_csr;

// ---------------------------------------------------------------------------
// Sense-reversing inter-block barrier. Safe because grid == one resident
// wave (444 blocks, 3/SM guaranteed by launch bounds + 47.4KB static smem).
// ---------------------------------------------------------------------------
__device__ __forceinline__ void bar_sync(unsigned* cnt, unsigned* sense,
                                         unsigned n, unsigned& ls) {
    __threadfence();                 // publish this thread's prior writes
    __syncthreads();
    if (threadIdx.x == 0) {
        ls ^= 1u;
        if (atomicAdd(cnt, 1u) == n - 1u) {
            atomicExch(cnt, 0u);
            atomicExch(sense, ls);
        } else {
            while (atomicAdd(sense, 0u) != ls) __nanosleep(64);
        }
    }
    __syncthreads();
    __threadfence();                 // acquire other blocks' writes
}

// ---------------------------------------------------------------------------
// Fused persistent kernel: GEMM (blocks 0..390) || CSR build (391..443),
// full-grid barrier, then aggregate by all blocks.
// ---------------------------------------------------------------------------
__global__ __launch_bounds__(256, 3) void fused_kernel(
    const float* __restrict__ h,
    const float* __restrict__ w,
    const float* __restrict__ norm,
    const int4*  __restrict__ src4,
    const int4*  __restrict__ dst4,
    const float* __restrict__ bias,
    float* __restrict__ out)
{
    __shared__ alignas(16) __half sB[64 * SBH];            // 33792 B
    __shared__ alignas(16) __half sAw[8][2][16 * AWS];     // 12288 B
    __shared__ int sScan[256];                             //  1024 B

    const int bid  = blockIdx.x;
    const int tid  = threadIdx.x;
    const int warp = tid >> 5;
    const int lane = tid & 31;
    const unsigned FULL = 0xFFFFFFFFu;

    unsigned lsAll = 0, lsCsr = 0;
    if (tid == 0) {
        lsAll = atomicAdd(&g_sense_all, 0u);
        lsCsr = atomicAdd(&g_sense_csr, 0u);
    }

    if (bid < GEMM_BLOCKS) {
        // ================= GEMM role (R13 validated body) =================
        const int g = lane >> 2;
        const int t = lane & 3;
        const int row0 = bid * 128;

        // stage full W once: w[k][n] (f32) -> sB[n][k] (f16)
#pragma unroll
        for (int i = 0; i < 16; i++) {
            const int fid = tid + 256 * i;
            const int k   = fid >> 4;
            const int n0  = (fid & 15) * 4;
            const float4 v = __ldg((const float4*)w + fid);
            sB[(n0 + 0) * SBH + k] = __float2half_rn(v.x);
            sB[(n0 + 1) * SBH + k] = __float2half_rn(v.y);
            sB[(n0 + 2) * SBH + k] = __float2half_rn(v.z);
            sB[(n0 + 3) * SBH + k] = __float2half_rn(v.w);
        }
        __syncthreads();

        const int r0 = row0 + warp * 16 + g;
        const int r1 = r0 + 8;
        const bool ok0 = (r0 < N_NODES);
        const bool ok1 = (r1 < N_NODES);
        const float* pA0 = h + (size_t)r0 * IN_F + 4 * t;
        const float* pA1 = h + (size_t)r1 * IN_F + 4 * t;

        const uint32_t rowp = (uint32_t)(((lane >> 3) & 1) * 8 + (lane & 7));
        const uint32_t acol = (uint32_t)((lane >> 4) * 8);
        uint32_t aSlab[2];
#pragma unroll
        for (int st = 0; st < 2; st++)
            aSlab[st] = (uint32_t)__cvta_generic_to_shared(&sAw[warp][st][0]) +
                        (rowp * AWS + acol) * 2;

        const uint32_t sB_u = (uint32_t)__cvta_generic_to_shared(sB);
        const uint32_t bRow = (uint32_t)((lane >> 4) * 8 + (lane & 7));
        const uint32_t bCol = (uint32_t)(((lane >> 3) & 1) * 8);
        uint32_t bAddr[4];
#pragma unroll
        for (int np = 0; np < 4; np++)
            bAddr[np] = sB_u + ((np * 16 + bRow) * SBH + bCol) * 2;

        float acc[8][4];
#pragma unroll
        for (int i = 0; i < 8; i++)
#pragma unroll
            for (int j = 0; j < 4; j++) acc[i][j] = 0.f;

        const float4 z4 = make_float4(0.f, 0.f, 0.f, 0.f);
        float4 fR[2][2];

#define LDG_A(buf, s)                                                        \
        do {                                                                 \
            const int kb = (s) * 16;                                         \
            fR[buf][0] = ok0 ? __ldg((const float4*)(pA0 + kb)) : z4;        \
            fR[buf][1] = ok1 ? __ldg((const float4*)(pA1 + kb)) : z4;        \
        } while (0)

        LDG_A(0, 0);
        LDG_A(1, 1);

#pragma unroll
        for (int s = 0; s < 16; s++) {
            const int buf = s & 1;
            {
                __half2 p0 = __floats2half2_rn(fR[buf][0].x, fR[buf][0].y);
                __half2 p1 = __floats2half2_rn(fR[buf][0].z, fR[buf][0].w);
                __half2 q0 = __floats2half2_rn(fR[buf][1].x, fR[buf][1].y);
                __half2 q1 = __floats2half2_rn(fR[buf][1].z, fR[buf][1].w);
                uint2 u0, u1;
                u0.x = *(uint32_t*)&p0; u0.y = *(uint32_t*)&p1;
                u1.x = *(uint32_t*)&q0; u1.y = *(uint32_t*)&q1;
                *(uint2*)(&sAw[warp][buf][(g    ) * AWS + 4 * t]) = u0;
                *(uint2*)(&sAw[warp][buf][(g + 8) * AWS + 4 * t]) = u1;
            }
            if (s < 14) LDG_A(buf, s + 2);
            __syncwarp();

            uint32_t a0, a1, a2, a3;
            asm volatile(
                "ldmatrix.sync.aligned.m8n8.x4.shared.b16 {%0,%1,%2,%3}, [%4];"
                : "=r"(a0), "=r"(a1), "=r"(a2), "=r"(a3)
                : "r"(aSlab[buf]));

#pragma unroll
            for (int np = 0; np < 4; np++) {
                uint32_t b0, b1, b2, b3;
                asm volatile(
                    "ldmatrix.sync.aligned.m8n8.x4.shared.b16 {%0,%1,%2,%3}, [%4];"
                    : "=r"(b0), "=r"(b1), "=r"(b2), "=r"(b3)
                    : "r"(bAddr[np] + s * 32));
                asm volatile(
                    "mma.sync.aligned.m16n8k16.row.col.f32.f16.f16.f32 "
                    "{%0,%1,%2,%3}, {%4,%5,%6,%7}, {%8,%9}, {%0,%1,%2,%3};"
                    : "+f"(acc[np * 2][0]), "+f"(acc[np * 2][1]),
                      "+f"(acc[np * 2][2]), "+f"(acc[np * 2][3])
                    : "r"(a0), "r"(a1), "r"(a2), "r"(a3), "r"(b0), "r"(b1));
                asm volatile(
                    "mma.sync.aligned.m16n8k16.row.col.f32.f16.f16.f32 "
                    "{%0,%1,%2,%3}, {%4,%5,%6,%7}, {%8,%9}, {%0,%1,%2,%3};"
                    : "+f"(acc[np * 2 + 1][0]), "+f"(acc[np * 2 + 1][1]),
                      "+f"(acc[np * 2 + 1][2]), "+f"(acc[np * 2 + 1][3])
                    : "r"(a0), "r"(a1), "r"(a2), "r"(a3), "r"(b2), "r"(b3));
            }
            __syncwarp();
        }

        const float nv0 = ok0 ? __ldg(norm + r0) : 0.f;
        const float nv1 = ok1 ? __ldg(norm + r1) : 0.f;
        __half2* __restrict__ hw2 = (__half2*)g_hw;
#pragma unroll
        for (int nt = 0; nt < 8; nt++) {
            const int c2 = nt * 4 + t;
            if (ok0)
                hw2[(size_t)r0 * 32 + c2] =
                    __floats2half2_rn(acc[nt][0] * nv0, acc[nt][1] * nv0);
            if (ok1)
                hw2[(size_t)r1 * 32 + c2] =
                    __floats2half2_rn(acc[nt][2] * nv1, acc[nt][3] * nv1);
        }
    } else {
        // ================= CSR role (53 blocks) =================
        const int cb = bid - GEMM_BLOCKS;          // 0..52
        const int stride = CSR_BLOCKS * 256;       // 13568

        // --- hist + slot recording
        for (int i = cb * 256 + tid; i < E4; i += stride) {
            const int4 d = __ldg(dst4 + i);
            int4 sl;
            sl.x = atomicAdd(&g_deg[d.x], 1);
            sl.y = atomicAdd(&g_deg[d.y], 1);
            sl.z = atomicAdd(&g_deg[d.z], 1);
            sl.w = atomicAdd(&g_deg[d.w], 1);
            ((int4*)g_slot)[i] = sl;
        }
        bar_sync(&g_cnt_csr, &g_sense_csr, CSR_BLOCKS, lsCsr);

        // --- scan A: per-thread 4 nodes, block scan, block sum
        const int nb = (cb * 256 + tid) * 4;       // node base (max 54268)
        int v0 = (nb + 0 < N_NODES) ? g_deg[nb + 0] : 0;
        int v1 = (nb + 1 < N_NODES) ? g_deg[nb + 1] : 0;
        int v2 = (nb + 2 < N_NODES) ? g_deg[nb + 2] : 0;
        int v3 = (nb + 3 < N_NODES) ? g_deg[nb + 3] : 0;
        const int s4 = v0 + v1 + v2 + v3;
        sScan[tid] = s4;
        __syncthreads();
        for (int off = 1; off < 256; off <<= 1) {
            int x = (tid >= off) ? sScan[tid - off] : 0;
            __syncthreads();
            sScan[tid] += x;
            __syncthreads();
        }
        const int excl = sScan[tid] - s4;
        if (tid == 255) g_bsum[cb] = sScan[255];
        bar_sync(&g_cnt_csr, &g_sense_csr, CSR_BLOCKS, lsCsr);

        // --- scan B: block cb==0, warp 0 scans the 53 block sums
        if (cb == 0 && warp == 0) {
            const int va = (lane < CSR_BLOCKS) ? g_bsum[lane] : 0;
            const int vb = (lane + 32 < CSR_BLOCKS) ? g_bsum[lane + 32] : 0;
            int a = va, b = vb;
            for (int off = 1; off < 32; off <<= 1) {
                int x = __shfl_up_sync(FULL, a, off);
                if (lane >= off) a += x;
            }
            const int totA = __shfl_sync(FULL, a, 31);
            for (int off = 1; off < 32; off <<= 1) {
                int x = __shfl_up_sync(FULL, b, off);
                if (lane >= off) b += x;
            }
            b += totA;
            if (lane < CSR_BLOCKS) g_boff[lane] = a - va;
            if (lane + 32 < CSR_BLOCKS) g_boff[lane + 32] = b - vb;
        }
        bar_sync(&g_cnt_csr, &g_sense_csr, CSR_BLOCKS, lsCsr);

        // --- scan C: write row starts
        int base = g_boff[cb] + excl;
        if (nb + 0 < N_NODES) { g_start[nb + 0] = base; base += v0; }
        if (nb + 1 < N_NODES) { g_start[nb + 1] = base; base += v1; }
        if (nb + 2 < N_NODES) { g_start[nb + 2] = base; base += v2; }
        if (nb + 3 < N_NODES) { g_start[nb + 3] = base; base += v3; }
        bar_sync(&g_cnt_csr, &g_sense_csr, CSR_BLOCKS, lsCsr);

        // --- atomic-free fill
        for (int i = cb * 256 + tid; i < E4; i += stride) {
            const int4 d  = __ldg(dst4 + i);
            const int4 sl = ((const int4*)g_slot)[i];
            const int4 s  = __ldg(src4 + i);
            g_esrc[g_start[d.x] + sl.x] = s.x;
            g_esrc[g_start[d.y] + sl.y] = s.y;
            g_esrc[g_start[d.z] + sl.z] = s.z;
            g_esrc[g_start[d.w] + sl.w] = s.w;
        }
    }

    // ================= full-grid barrier, then aggregate =================
    bar_sync(&g_cnt_all, &g_sense_all, NB, lsAll);

    // Aggregate (R10 validated body), grid-strided: 4 nodes per warp.
    const int half = lane >> 4;
    const int fl   = lane & 15;
    const int gwarp = bid * 8 + warp;
    const uint2* __restrict__ hwq = (const uint2*)g_hw;

    for (int gid = gwarp; gid < N_NODES / 4; gid += NB * 8) {
        const int nbase = gid * 4;

        int st = 0, dg = 0;
        if (lane < 4) {
            st = g_start[nbase + lane];
            dg = g_deg[nbase + lane];
            g_deg[nbase + lane] = 0;     // restore invariant for next call
        }
        const int stA = __shfl_sync(FULL, st, half);
        const int dgA = __shfl_sync(FULL, dg, half);
        const int stB = __shfl_sync(FULL, st, 2 + half);
        const int dgB = __shfl_sync(FULL, dg, 2 + half);
        const int d0 = __shfl_sync(FULL, dg, 0), d1 = __shfl_sync(FULL, dg, 1);
        const int d2 = __shfl_sync(FULL, dg, 2), d3 = __shfl_sync(FULL, dg, 3);
        const int m = max(max(d0, d1), max(d2, d3));

        float4 aA = make_float4(0.f, 0.f, 0.f, 0.f);
        float4 aB = make_float4(0.f, 0.f, 0.f, 0.f);

        for (int b = 0; b < m; b += 16) {
            const int iA = (b + fl < dgA) ? __ldg(g_esrc + stA + b + fl) : 0;
            const int iB = (b + fl < dgB) ? __ldg(g_esrc + stB + b + fl) : 0;
#pragma unroll
            for (int j = 0; j < 16; j++) {
                const int sa = __shfl_sync(FULL, iA, (half << 4) + j);
                const int sb = __shfl_sync(FULL, iB, (half << 4) + j);
                if (b + j < dgA) {
                    const uint2 v = __ldg(hwq + (size_t)sa * 16 + fl);
                    const float2 p0 = __half22float2(*(const __half2*)&v.x);
                    const float2 p1 = __half22float2(*(const __half2*)&v.y);
                    aA.x += p0.x; aA.y += p0.y; aA.z += p1.x; aA.w += p1.y;
                }
                if (b + j < dgB) {
                    const uint2 v = __ldg(hwq + (size_t)sb * 16 + fl);
                    const float2 p0 = __half22float2(*(const __half2*)&v.x);
                    const float2 p1 = __half22float2(*(const __half2*)&v.y);
                    aB.x += p0.x; aB.y += p0.y; aB.z += p1.x; aB.w += p1.y;
                }
            }
        }

        const int nodeA = nbase + half;
        const int nodeB = nbase + 2 + half;
        const float nA = __ldg(norm + nodeA);
        const float nBv = __ldg(norm + nodeB);
        const float4 bi = ((const float4*)bias)[fl];
        float4 rA, rB;
        rA.x = fmaxf(fmaf(aA.x, nA, bi.x), 0.f);
        rA.y = fmaxf(fmaf(aA.y, nA, bi.y), 0.f);
        rA.z = fmaxf(fmaf(aA.z, nA, bi.z), 0.f);
        rA.w = fmaxf(fmaf(aA.w, nA, bi.w), 0.f);
        rB.x = fmaxf(fmaf(aB.x, nBv, bi.x), 0.f);
        rB.y = fmaxf(fmaf(aB.y, nBv, bi.y), 0.f);
        rB.z = fmaxf(fmaf(aB.z, nBv, bi.z), 0.f);
        rB.w = fmaxf(fmaf(aB.w, nBv, bi.w), 0.f);
        ((float4*)out)[(size_t)nodeA * 16 + fl] = rA;
        ((float4*)out)[(size_t)nodeB * 16 + fl] = rB;
    }
}

// ---------------------------------------------------------------------------
extern "C" void kernel_launch(void* const* d_in, const int* in_sizes, int n_in,
                              void* d_out, int out_size)
{
    const float* h      = (const float*)d_in[0];
    const float* norm   = (const float*)d_in[1];
    const int*   src    = (const int*)d_in[2];
    const int*   dst    = (const int*)d_in[3];
    const float* weight = (const float*)d_in[4];
    const float* bias   = (const float*)d_in[5];
    float* out = (float*)d_out;

    fused_kernel<<<NB, 256>>>(h, weight, norm,
                              (const int4*)src, (const int4*)dst,
                              bias, out);
}

// round 15
// speedup vs baseline: 1.7050x; 1.7050x over previous
#include <cuda_runtime.h>
#include <cuda_fp16.h>
#include <cstdint>

#define N_NODES 50000
#define N_EDGES 800000
#define IN_F    256
#define OUT_F   64
#define N_PAD   50176      // 1024 * 49, padded node count for the scan
#define SCAN_SMEM (N_PAD * 4)
#define E4 (N_EDGES / 4)   // 200000
#define GEMM_BLOCKS 391    // ceil(50000/128)
#define SBH 264            // sB stride in halves (256 + 8) -> LDSM conflict-free
#define AWS 24             // per-warp A slab row stride in halves (16+8 pad)

// Scratch (device globals: allocation-guard compliant, zero-init at load)
__device__ __half g_hw[(size_t)N_NODES * OUT_F];  // projected*norm feats (fp16)
__device__ int    g_deg[N_NODES];                 // in-degree (zeroed by aggregate)
__device__ int    g_start[N_NODES];               // CSR row starts
__device__ int    g_slot[N_EDGES];                // per-edge slot within dst bucket
__device__ int    g_esrc[N_EDGES];                // src ids bucketed by dst

// ---------------------------------------------------------------------------
// Histogram + slot recording (side stream, concurrent with GEMM)
// ---------------------------------------------------------------------------
__global__ __launch_bounds__(256) void hist_kernel(const int4* __restrict__ dst4) {
    const int i = blockIdx.x * 256 + threadIdx.x;
    if (i >= E4) return;
    const int4 d = __ldg(dst4 + i);
    int4 sl;
    sl.x = atomicAdd(&g_deg[d.x], 1);
    sl.y = atomicAdd(&g_deg[d.y], 1);
    sl.z = atomicAdd(&g_deg[d.z], 1);
    sl.w = atomicAdd(&g_deg[d.w], 1);
    ((int4*)g_slot)[i] = sl;
}

// ---------------------------------------------------------------------------
// Single-block exclusive scan of g_deg -> g_start
// ---------------------------------------------------------------------------
__global__ __launch_bounds__(1024) void scan_kernel() {
    extern __shared__ int sh[];          // N_PAD ints
    __shared__ int ssum[1024];
    const int t = threadIdx.x;

    for (int i = t; i < N_PAD; i += 1024)
        sh[i] = (i < N_NODES) ? g_deg[i] : 0;
    __syncthreads();

    const int base = t * 49;
    int s = 0;
#pragma unroll
    for (int i = 0; i < 49; i++) s += sh[base + i];
    ssum[t] = s;
    __syncthreads();

    for (int off = 1; off < 1024; off <<= 1) {
        int x = (t >= off) ? ssum[t - off] : 0;
        __syncthreads();
        ssum[t] += x;
        __syncthreads();
    }

    int run = ssum[t] - s;
#pragma unroll
    for (int i = 0; i < 49; i++) {
        int v = sh[base + i];
        sh[base + i] = run;
        run += v;
    }
    __syncthreads();

    for (int i = t; i < N_NODES; i += 1024)
        g_start[i] = sh[i];
}

// ---------------------------------------------------------------------------
// Atomic-free fill: g_esrc[g_start[dst] + slot] = src   (4 edges per thread)
// ---------------------------------------------------------------------------
__global__ __launch_bounds__(256) void fill_kernel(
    const int4* __restrict__ src4,
    const int4* __restrict__ dst4)
{
    const int i = blockIdx.x * 256 + threadIdx.x;
    if (i >= E4) return;
    const int4 d  = __ldg(dst4 + i);
    const int4 sl = ((const int4*)g_slot)[i];
    const int4 s  = __ldg(src4 + i);
    g_esrc[g_start[d.x] + sl.x] = s.x;
    g_esrc[g_start[d.y] + sl.y] = s.y;
    g_esrc[g_start[d.z] + sl.z] = s.z;
    g_esrc[g_start[d.w] + sl.w] = s.w;
}

// ---------------------------------------------------------------------------
// fp16 GEMM + fold norm (R13 validated body, unchanged):
// LDG.128 A loads restaged through per-warp smem slab, depth-2 ring,
// no block barriers in the mainloop.
// ---------------------------------------------------------------------------
__global__ __launch_bounds__(256, 3) void gemm_f16_kernel(
    const float* __restrict__ h,
    const float* __restrict__ w,
    const float* __restrict__ norm)
{
    __shared__ alignas(16) __half sB[64 * SBH];
    __shared__ alignas(16) __half sAw[8][2][16 * AWS];  // warp x stage x slab

    const int tid  = threadIdx.x;
    const int warp = tid >> 5;
    const int lane = tid & 31;
    const int g    = lane >> 2;
    const int t    = lane & 3;
    const int row0 = blockIdx.x * 128;

    // ---- stage full W once: w[k][n] (f32) -> sB[n][k] (f16)
#pragma unroll
    for (int i = 0; i < 16; i++) {
        const int fid = tid + 256 * i;        // float4 id, 0..4095
        const int k   = fid >> 4;             // 0..255
        const int n0  = (fid & 15) * 4;
        const float4 v = __ldg((const float4*)w + fid);
        sB[(n0 + 0) * SBH + k] = __float2half_rn(v.x);
        sB[(n0 + 1) * SBH + k] = __float2half_rn(v.y);
        sB[(n0 + 2) * SBH + k] = __float2half_rn(v.z);
        sB[(n0 + 3) * SBH + k] = __float2half_rn(v.w);
    }
    __syncthreads();

    const int r0 = row0 + warp * 16 + g;
    const int r1 = r0 + 8;
    const bool ok0 = (r0 < N_NODES);
    const bool ok1 = (r1 < N_NODES);
    const float* pA0 = h + (size_t)r0 * IN_F + 4 * t;
    const float* pA1 = h + (size_t)r1 * IN_F + 4 * t;

    const uint32_t rowp = (uint32_t)(((lane >> 3) & 1) * 8 + (lane & 7));
    const uint32_t acol = (uint32_t)((lane >> 4) * 8);
    uint32_t aSlab[2];
#pragma unroll
    for (int st = 0; st < 2; st++)
        aSlab[st] = (uint32_t)__cvta_generic_to_shared(&sAw[warp][st][0]) +
                    (rowp * AWS + acol) * 2;

    const uint32_t sB_u = (uint32_t)__cvta_generic_to_shared(sB);
    const uint32_t bRow = (uint32_t)((lane >> 4) * 8 + (lane & 7));
    const uint32_t bCol = (uint32_t)(((lane >> 3) & 1) * 8);
    uint32_t bAddr[4];
#pragma unroll
    for (int np = 0; np < 4; np++)
        bAddr[np] = sB_u + ((np * 16 + bRow) * SBH + bCol) * 2;

    float acc[8][4];
#pragma unroll
    for (int i = 0; i < 8; i++)
#pragma unroll
        for (int j = 0; j < 4; j++) acc[i][j] = 0.f;

    const float4 z4 = make_float4(0.f, 0.f, 0.f, 0.f);
    float4 fR[2][2];                          // depth-2 ring, 2 rows each

#define LDG_A(buf, s)                                                        \
    do {                                                                     \
        const int kb = (s) * 16;                                             \
        fR[buf][0] = ok0 ? __ldg((const float4*)(pA0 + kb)) : z4;            \
        fR[buf][1] = ok1 ? __ldg((const float4*)(pA1 + kb)) : z4;            \
    } while (0)

    LDG_A(0, 0);
    LDG_A(1, 1);

#pragma unroll
    for (int s = 0; s < 16; s++) {
        const int buf = s & 1;
        {
            __half2 p0 = __floats2half2_rn(fR[buf][0].x, fR[buf][0].y);
            __half2 p1 = __floats2half2_rn(fR[buf][0].z, fR[buf][0].w);
            __half2 q0 = __floats2half2_rn(fR[buf][1].x, fR[buf][1].y);
            __half2 q1 = __floats2half2_rn(fR[buf][1].z, fR[buf][1].w);
            uint2 u0, u1;
            u0.x = *(uint32_t*)&p0; u0.y = *(uint32_t*)&p1;
            u1.x = *(uint32_t*)&q0; u1.y = *(uint32_t*)&q1;
            *(uint2*)(&sAw[warp][buf][(g    ) * AWS + 4 * t]) = u0;
            *(uint2*)(&sAw[warp][buf][(g + 8) * AWS + 4 * t]) = u1;
        }
        if (s < 14) LDG_A(buf, s + 2);
        __syncwarp();

        uint32_t a0, a1, a2, a3;
        asm volatile(
            "ldmatrix.sync.aligned.m8n8.x4.shared.b16 {%0,%1,%2,%3}, [%4];"
            : "=r"(a0), "=r"(a1), "=r"(a2), "=r"(a3)
            : "r"(aSlab[buf]));

#pragma unroll
        for (int np = 0; np < 4; np++) {
            uint32_t b0, b1, b2, b3;
            asm volatile(
                "ldmatrix.sync.aligned.m8n8.x4.shared.b16 {%0,%1,%2,%3}, [%4];"
                : "=r"(b0), "=r"(b1), "=r"(b2), "=r"(b3)
                : "r"(bAddr[np] + s * 32));
            asm volatile(
                "mma.sync.aligned.m16n8k16.row.col.f32.f16.f16.f32 "
                "{%0,%1,%2,%3}, {%4,%5,%6,%7}, {%8,%9}, {%0,%1,%2,%3};"
                : "+f"(acc[np * 2][0]), "+f"(acc[np * 2][1]),
                  "+f"(acc[np * 2][2]), "+f"(acc[np * 2][3])
                : "r"(a0), "r"(a1), "r"(a2), "r"(a3), "r"(b0), "r"(b1));
            asm volatile(
                "mma.sync.aligned.m16n8k16.row.col.f32.f16.f16.f32 "
                "{%0,%1,%2,%3}, {%4,%5,%6,%7}, {%8,%9}, {%0,%1,%2,%3};"
                : "+f"(acc[np * 2 + 1][0]), "+f"(acc[np * 2 + 1][1]),
                  "+f"(acc[np * 2 + 1][2]), "+f"(acc[np * 2 + 1][3])
                : "r"(a0), "r"(a1), "r"(a2), "r"(a3), "r"(b2), "r"(b3));
        }
        __syncwarp();   // all lanes done reading slab[buf] before next refill
    }

    // Epilogue: scale by norm[row], convert to fp16, store half2 pairs
    const float nv0 = ok0 ? __ldg(norm + r0) : 0.f;
    const float nv1 = ok1 ? __ldg(norm + r1) : 0.f;
    __half2* __restrict__ hw2 = (__half2*)g_hw;   // 32 half2 per node row
#pragma unroll
    for (int nt = 0; nt < 8; nt++) {
        const int c2 = nt * 4 + t;                // half2 column index
        if (ok0)
            hw2[(size_t)r0 * 32 + c2] =
                __floats2half2_rn(acc[nt][0] * nv0, acc[nt][1] * nv0);
        if (ok1)
            hw2[(size_t)r1 * 32 + c2] =
                __floats2half2_rn(acc[nt][2] * nv1, acc[nt][3] * nv1);
    }
}

// ---------------------------------------------------------------------------
// Aggregate: 4 nodes per warp via 8-lane groups; each lane gathers LDG.128
// (16 bytes of the 128-byte fp16 row).  One warp gather instruction now
// moves 512 B = 4 edges (vs 256 B before): half the LSU issues, double the
// edges in flight.  fp32 accumulation; restores g_deg = 0.
// ---------------------------------------------------------------------------
__global__ __launch_bounds__(256) void aggregate_kernel(
    const float* __restrict__ norm,
    const float* __restrict__ bias,
    float* __restrict__ out)
{
    const unsigned FULL = 0xFFFFFFFFu;
    const int wid  = (blockIdx.x * 256 + threadIdx.x) >> 5;
    const int base = wid * 4;
    if (base >= N_NODES) return;         // N_NODES % 4 == 0: uniform per warp
    const int lane  = threadIdx.x & 31;
    const int group = lane >> 3;         // 0..3 -> node base+group
    const int fl    = lane & 7;          // 16-byte chunk within the row

    int st = 0, dg = 0;
    if (lane < 4) {
        st = g_start[base + lane];
        dg = g_deg[base + lane];
        g_deg[base + lane] = 0;          // restore invariant for next call
    }
    const int stG = __shfl_sync(FULL, st, group);
    const int dgG = __shfl_sync(FULL, dg, group);
    const int d0 = __shfl_sync(FULL, dg, 0), d1 = __shfl_sync(FULL, dg, 1);
    const int d2 = __shfl_sync(FULL, dg, 2), d3 = __shfl_sync(FULL, dg, 3);
    const int m = max(max(d0, d1), max(d2, d3));

    const uint4* __restrict__ hwq = (const uint4*)g_hw;  // 8 uint4 per row

    float acc[8];
#pragma unroll
    for (int i = 0; i < 8; i++) acc[i] = 0.f;

    for (int b = 0; b < m; b += 8) {
        // 8 indices per group, loaded coalesced by the group's 8 lanes
        const int idx = (b + fl < dgG) ? __ldg(g_esrc + stG + b + fl) : 0;
#pragma unroll
        for (int j = 0; j < 8; j++) {
            const int s = __shfl_sync(FULL, idx, (group << 3) + j);
            if (b + j < dgG) {
                const uint4 v = __ldg(hwq + (size_t)s * 8 + fl);
                const float2 p0 = __half22float2(*(const __half2*)&v.x);
                const float2 p1 = __half22float2(*(const __half2*)&v.y);
                const float2 p2 = __half22float2(*(const __half2*)&v.z);
                const float2 p3 = __half22float2(*(const __half2*)&v.w);
                acc[0] += p0.x; acc[1] += p0.y;
                acc[2] += p1.x; acc[3] += p1.y;
                acc[4] += p2.x; acc[5] += p2.y;
                acc[6] += p3.x; acc[7] += p3.y;
            }
        }
    }

    const int node = base + group;
    const float nv = __ldg(norm + node);
    const float4 bi0 = ((const float4*)bias)[fl * 2];
    const float4 bi1 = ((const float4*)bias)[fl * 2 + 1];
    float4 r0, r1;
    r0.x = fmaxf(fmaf(acc[0], nv, bi0.x), 0.f);
    r0.y = fmaxf(fmaf(acc[1], nv, bi0.y), 0.f);
    r0.z = fmaxf(fmaf(acc[2], nv, bi0.z), 0.f);
    r0.w = fmaxf(fmaf(acc[3], nv, bi0.w), 0.f);
    r1.x = fmaxf(fmaf(acc[4], nv, bi1.x), 0.f);
    r1.y = fmaxf(fmaf(acc[5], nv, bi1.y), 0.f);
    r1.z = fmaxf(fmaf(acc[6], nv, bi1.z), 0.f);
    r1.w = fmaxf(fmaf(acc[7], nv, bi1.w), 0.f);
    ((float4*)out)[(size_t)node * 16 + fl * 2]     = r0;
    ((float4*)out)[(size_t)node * 16 + fl * 2 + 1] = r1;
}

// ---------------------------------------------------------------------------
extern "C" void kernel_launch(void* const* d_in, const int* in_sizes, int n_in,
                              void* d_out, int out_size)
{
    const float* h      = (const float*)d_in[0];
    const float* norm   = (const float*)d_in[1];
    const int*   src    = (const int*)d_in[2];
    const int*   dst    = (const int*)d_in[3];
    const float* weight = (const float*)d_in[4];
    const float* bias   = (const float*)d_in[5];
    float* out = (float*)d_out;

    static cudaStream_t sB = nullptr;
    static cudaEvent_t  evFork = nullptr, evJoin = nullptr;
    if (sB == nullptr) {
        cudaStreamCreateWithFlags(&sB, cudaStreamNonBlocking);
        cudaEventCreateWithFlags(&evFork, cudaEventDisableTiming);
        cudaEventCreateWithFlags(&evJoin, cudaEventDisableTiming);
        cudaFuncSetAttribute(scan_kernel,
                             cudaFuncAttributeMaxDynamicSharedMemorySize,
                             SCAN_SMEM);
    }

    // Fork: CSR build on side stream, concurrent with the GEMM.
    cudaEventRecord(evFork, 0);
    cudaStreamWaitEvent(sB, evFork, 0);
    hist_kernel<<<(E4 + 255) / 256, 256, 0, sB>>>((const int4*)dst);
    scan_kernel<<<1, 1024, SCAN_SMEM, sB>>>();
    fill_kernel<<<(E4 + 255) / 256, 256, 0, sB>>>((const int4*)src,
                                                  (const int4*)dst);
    cudaEventRecord(evJoin, sB);

    // GEMM on the main stream (concurrent with CSR build).
    gemm_f16_kernel<<<GEMM_BLOCKS, 256>>>(h, weight, norm);

    // Join, then aggregate (+ fused norm/bias/relu epilogue).
    cudaStreamWaitEvent(0, evJoin, 0);
    {
        const int warps  = N_NODES / 4;          // 12500
        const int blocks = (warps * 32 + 255) / 256;
        aggregate_kernel<<<blocks, 256>>>(norm, bias, out);
    }
}